// round 17
// baseline (speedup 1.0000x reference)
#include <cuda_runtime.h>
#include <math.h>

#define Lc 8
#define Pc 8
#define Sc 128
#define Bc 16
#define Wc 768
#define Mc 64
#define W4   (Wc / 4)            // 192 float4 per W row == NTHR
#define ROW4 ((Bc * Wc) / 4)     // s-stride in float4 = 3072
#define NBLK (Lc * Pc * Bc)      // 1024
#define NTHR 192

// Scratch (allocation-free device globals)
// g_sem: zeroed by each replay AT ENTRY (producers need >=50us of streaming
// before their first atomicAdd; launch skew within the single wave is <5us,
// so zeroing always completes first). Accumulated via REDG during phase 1,
// read by phase 3 after the barrier. Deterministic, same work every call.
__device__ float    g_sem[Lc * Bc * Wc];    // [l,b,w] unnormalized sem (384 KB)
__device__ float    g_e[Lc * Pc * Bc];      // e = exp(sigmoid(score)) per (l,p,b)
__device__ unsigned g_cnt;                  // barrier count
__device__ unsigned g_gen;                  // barrier generation (monotonic)

// ---------------------------------------------------------------------------
// ONE fused kernel: 1024 CTAs x 192 threads, single wave (occ 8/SM possible,
// 148*8=1184 >= 1024 -> gen-counting global barrier is deadlock-free).
//   entry  : zero g_sem slice (replay reset)
//   phase 1: stream embeds (R3-proven __ldcs/unroll8/dual-dot loop),
//            score -> e, REDG e*max into g_sem
//   barrier: one global generation-counting barrier
//   phase 3: CTA (lp,b) emits out[b, m=lp, 0..W) -- all CTAs busy
// ---------------------------------------------------------------------------
__global__ __launch_bounds__(NTHR, 8)
void fused_kernel(const float* __restrict__ embeds,
                  const float* __restrict__ mask,
                  const float* __restrict__ w0,
                  const float* __restrict__ b0,
                  const float* __restrict__ w1,
                  const float* __restrict__ b1,
                  float* __restrict__ out)
{
    __shared__ float sw1[Sc];
    __shared__ float sred[6];
    __shared__ float s_e;
    __shared__ float s_ev[Lc * Pc];
    __shared__ float s_mw[Lc];

    const int t   = threadIdx.x;            // 0..191
    const int lpb = blockIdx.x;             // (l*P+p)*B + b
    const int b   = lpb & (Bc - 1);
    const int lp  = lpb >> 4;               // l*8 + p  (also the output m)
    const int l   = lp >> 3;

    // ---- entry: zero this replay's g_sem (coalesced, disjoint) ------------
    {
        const int gtid = lpb * NTHR + t;
        if (gtid < Lc * Bc * Wc) g_sem[gtid] = 0.0f;
    }
    __threadfence();                        // push the zeroing into L2

    if (t < Sc) sw1[t] = __ldg(w1 + t);
    __syncthreads();

    // ===================== Phase 1: stream embeds (402 MB) =================
    {
        const float4* base = reinterpret_cast<const float4*>(embeds)
                           + (size_t)lp * Sc * ROW4 + (size_t)b * W4 + t;
        const float4 w0v = __ldg(reinterpret_cast<const float4*>(w0) + t);

        float4 mx = make_float4(-3.4e38f, -3.4e38f, -3.4e38f, -3.4e38f);
        float dot0 = 0.0f, dot1 = 0.0f;

        #pragma unroll 8
        for (int s = 0; s < Sc; s += 2) {
            float4 v0 = __ldcs(base + (size_t)s * ROW4);
            float4 v1 = __ldcs(base + (size_t)(s + 1) * ROW4);
            mx.x = fmaxf(mx.x, fmaxf(v0.x, v1.x));
            mx.y = fmaxf(mx.y, fmaxf(v0.y, v1.y));
            mx.z = fmaxf(mx.z, fmaxf(v0.z, v1.z));
            mx.w = fmaxf(mx.w, fmaxf(v0.w, v1.w));
            dot0 += (v0.x * w0v.x + v0.y * w0v.y + v0.z * w0v.z + v0.w * w0v.w) * sw1[s];
            dot1 += (v1.x * w0v.x + v1.y * w0v.y + v1.z * w0v.z + v1.w * w0v.w) * sw1[s + 1];
        }

        float dot = dot0 + dot1;
        #pragma unroll
        for (int o = 16; o > 0; o >>= 1)
            dot += __shfl_down_sync(0xffffffffu, dot, o);
        if ((t & 31) == 0) sred[t >> 5] = dot;
        __syncthreads();

        // warp 0: parallel bias sum + score -> e
        if (t < 32) {
            float sw = sw1[t] + sw1[t + 32] + sw1[t + 64] + sw1[t + 96];
            #pragma unroll
            for (int o = 16; o > 0; o >>= 1)
                sw += __shfl_down_sync(0xffffffffu, sw, o);
            if (t == 0) {
                float score = sred[0] + sred[1] + sred[2] + sred[3] + sred[4] + sred[5]
                            + b0[0] * sw + b1[0];
                float sig = 1.0f / (1.0f + __expf(-score));   // sigmoid in (0,1)
                float e   = __expf(sig);                      // softmax weight (unnorm)
                g_e[lpb] = e;
                s_e = e;
            }
        }
        __syncthreads();

        // accumulate e*max into sem[l,b,w] (4 coalesced REDG.F32 per thread)
        const float e = s_e;
        float* semp = g_sem + ((size_t)l * Bc + b) * Wc + 4 * t;
        atomicAdd(semp + 0, e * mx.x);
        atomicAdd(semp + 1, e * mx.y);
        atomicAdd(semp + 2, e * mx.z);
        atomicAdd(semp + 3, e * mx.w);
    }

    // ===================== ONE global barrier ==============================
    __syncthreads();
    if (t == 0) {
        __threadfence();                                   // publish sem/e
        volatile unsigned* genp = &g_gen;
        unsigned g = *genp;                                // read BEFORE arrive
        if (atomicAdd(&g_cnt, 1u) == NBLK - 1) {
            g_cnt = 0;
            __threadfence();
            atomicAdd(&g_gen, 1u);                         // release
        } else {
            while (*genp == g) __nanosleep(64);
        }
        __threadfence();                                   // acquire
    }
    __syncthreads();

    // ===================== Phase 3: out[b, m=lp, w4=t] ======================
    {
        const int m = lp;                                  // 0..63

        // e values for this b -> smem (64 loads by 64 threads)
        if (t < Lc * Pc)
            s_ev[t] = __ldcg(g_e + t * Bc + b);
        __syncthreads();

        // folded weights: mw[l] = mask[b,l,m] / sum_p e[l,p]
        if (t < Lc) {
            float s = 0.0f;
            #pragma unroll
            for (int p = 0; p < Pc; p++) s += s_ev[t * Pc + p];
            s_mw[t] = __ldg(mask + ((size_t)b * Lc + t) * Mc + m) / s;
        }
        __syncthreads();

        float4 acc = make_float4(0.f, 0.f, 0.f, 0.f);
        #pragma unroll
        for (int ll = 0; ll < Lc; ll++) {
            const float mw = s_mw[ll];
            float4 sv = __ldcg(reinterpret_cast<const float4*>(g_sem)
                               + ((size_t)ll * Bc + b) * W4 + t);
            acc.x += mw * sv.x; acc.y += mw * sv.y;
            acc.z += mw * sv.z; acc.w += mw * sv.w;
        }
        reinterpret_cast<float4*>(out)[((size_t)b * Mc + m) * W4 + t] = acc;
    }
}

// ---------------------------------------------------------------------------
extern "C" void kernel_launch(void* const* d_in, const int* in_sizes, int n_in,
                              void* d_out, int out_size)
{
    const float* embeds = (const float*)d_in[0];  // [L,P,S,B,W]
    const float* mask   = (const float*)d_in[1];  // [B,L,M]
    const float* w0     = (const float*)d_in[2];  // [1,W]
    const float* b0     = (const float*)d_in[3];  // [1]
    const float* w1     = (const float*)d_in[4];  // [1,S]
    const float* b1     = (const float*)d_in[5];  // [1]
    float* out          = (float*)d_out;          // [B,M,W]

    fused_kernel<<<NBLK, NTHR>>>(embeds, mask, w0, b0, w1, b1, out);
}